// round 1
// baseline (speedup 1.0000x reference)
#include <cuda_runtime.h>
#include <cstdint>

// Problem sizes (fixed by reference)
#define S_DIM  1024
#define P_DIM  8
#define N_PTS  8192            // S*P flattened colors
#define L2E    1.4426950408889634f

#define Q_PER_THREAD 8
#define BLK          128
#define NCH          74        // key-axis chunks -> grid 8 x 74 = 592 blocks = 4/SM
#define MC           ((N_PTS + NCH - 1) / NCH)   // 111

// Static device scratch (no allocations allowed)
__device__ float4 g_aq[N_PTS];                 // {Ax, Ay, Az, |A|^2}  (A = log2e * a, a = sorted clipped palette)
__device__ float4 g_bq[N_PTS];                 // {|B|^2, -2Bx, -2By, -2Bz}  (B = log2e * b, b = comp)
__device__ float4 g_scratch[NCH * N_PTS];      // per-chunk partials {sum_w, accx, accy, accz}

// ---------------------------------------------------------------------------
// Phase 1a: per-column stable rank sort of the palette + scaled query prep.
// One block per palette column p (8 blocks, 1024 threads each).
// ---------------------------------------------------------------------------
__global__ void sort_prep_kernel(const float* __restrict__ pallet) {
    __shared__ float keys[S_DIM];
    const int p = blockIdx.x;
    const int s = threadIdx.x;

    const float* src = pallet + (s * P_DIM + p) * 3;
    float x = fminf(fmaxf(src[0] * 0.5f, 0.f), 1.f);
    float y = fminf(fmaxf(src[1] * 0.5f, 0.f), 1.f);
    float z = fminf(fmaxf(src[2] * 0.5f, 0.f), 1.f);

    const float key = x * x * 0.299f + y * y * 0.587f + z * z * 0.114f;
    keys[s] = key;
    __syncthreads();

    // Stable rank: #(smaller) + #(equal with lower index). Matches jnp.argsort.
    int rank = 0;
#pragma unroll 8
    for (int j = 0; j < S_DIM; j++) {
        float kj = keys[j];
        rank += (kj < key) || (kj == key && j < s);
    }

    const float Ax = x * L2E, Ay = y * L2E, Az = z * L2E;
    g_aq[rank * P_DIM + p] = make_float4(Ax, Ay, Az, Ax * Ax + Ay * Ay + Az * Az);
}

// ---------------------------------------------------------------------------
// Phase 1b: key/value prep for comp.
// ---------------------------------------------------------------------------
__global__ void prep_b_kernel(const float* __restrict__ comp) {
    int i = blockIdx.x * blockDim.x + threadIdx.x;
    if (i >= N_PTS) return;
    const float* b = comp + 3 * i;
    float Bx = b[0] * L2E, By = b[1] * L2E, Bz = b[2] * L2E;
    float B2 = Bx * Bx + By * By + Bz * Bz;
    g_bq[i] = make_float4(B2, -2.f * Bx, -2.f * By, -2.f * Bz);
}

// ---------------------------------------------------------------------------
// Phase 2: the 8192x8192 softmin sweep.
// grid (8, NCH). Each thread owns 8 queries, loops over this block's m-chunk.
// Per pair: 1 FADD + 3 FMA (sq), FMNMX, MUFU.SQRT, MUFU.EX2(-d), 4 acc FMAs.
// ---------------------------------------------------------------------------
__global__ void __launch_bounds__(BLK) softmin_kernel() {
    __shared__ float4 sb[MC];

    const int m0 = blockIdx.y * MC;
    const int mc = min(MC, N_PTS - m0);
    for (int i = threadIdx.x; i < mc; i += BLK) sb[i] = g_bq[m0 + i];
    __syncthreads();

    const int q0 = blockIdx.x * (BLK * Q_PER_THREAD) + threadIdx.x * Q_PER_THREAD;

    float Ax[Q_PER_THREAD], Ay[Q_PER_THREAD], Az[Q_PER_THREAD], A2[Q_PER_THREAD];
    float sw[Q_PER_THREAD], cx[Q_PER_THREAD], cy[Q_PER_THREAD], cz[Q_PER_THREAD];
#pragma unroll
    for (int q = 0; q < Q_PER_THREAD; q++) {
        float4 a = g_aq[q0 + q];
        Ax[q] = a.x; Ay[q] = a.y; Az[q] = a.z; A2[q] = a.w;
        sw[q] = 0.f; cx[q] = 0.f; cy[q] = 0.f; cz[q] = 0.f;
    }

    for (int i = 0; i < mc; i++) {
        const float4 b = sb[i];
#pragma unroll
        for (int q = 0; q < Q_PER_THREAD; q++) {
            // sq' = |A|^2 + |B|^2 - 2 A.B  (= log2e^2 * |a-b|^2)
            float s = fmaf(b.y, Ax[q], fmaf(b.z, Ay[q], fmaf(b.w, Az[q], b.x + A2[q])));
            s = fmaxf(s, 0.f);
            float d;
            asm("sqrt.approx.f32 %0, %1;" : "=f"(d) : "f"(s));    // d = log2e * dist
            float w;
            asm("ex2.approx.f32 %0, %1;" : "=f"(w) : "f"(-d));    // w = exp(-dist)
            sw[q] += w;
            cx[q] = fmaf(w, b.y, cx[q]);   // accumulates w * (-2*log2e*bx) etc.
            cy[q] = fmaf(w, b.z, cy[q]);
            cz[q] = fmaf(w, b.w, cz[q]);
        }
    }

    float4* dst = g_scratch + blockIdx.y * N_PTS + q0;
#pragma unroll
    for (int q = 0; q < Q_PER_THREAD; q++)
        dst[q] = make_float4(sw[q], cx[q], cy[q], cz[q]);
}

// ---------------------------------------------------------------------------
// Phase 3: combine chunk partials, compute closest, accumulate MSE.
// 64 blocks x 128 threads = 8192 threads, one query each. atomicAdd into d_out.
// ---------------------------------------------------------------------------
__global__ void reduce_kernel(float* __restrict__ out) {
    const int q = blockIdx.x * blockDim.x + threadIdx.x;

    float sw = 0.f, cx = 0.f, cy = 0.f, cz = 0.f;
#pragma unroll 2
    for (int ch = 0; ch < NCH; ch++) {
        float4 v = g_scratch[ch * N_PTS + q];
        sw += v.x; cx += v.y; cy += v.z; cz += v.w;
    }
    // closest_c = acc_c / (-2 * log2e * sum_w)
    const float inv = -1.f / (2.f * L2E * sw);
    float clx = cx * inv, cly = cy * inv, clz = cz * inv;

    float4 a = g_aq[q];
    const float invL = 1.f / L2E;
    float ex = a.x * invL - clx;
    float ey = a.y * invL - cly;
    float ez = a.z * invL - clz;
    float local = ex * ex + ey * ey + ez * ez;

    // block reduction
    __shared__ float red[BLK / 32];
    for (int off = 16; off > 0; off >>= 1)
        local += __shfl_down_sync(0xFFFFFFFFu, local, off);
    const int lane = threadIdx.x & 31, wid = threadIdx.x >> 5;
    if (lane == 0) red[wid] = local;
    __syncthreads();
    if (wid == 0) {
        local = (lane < BLK / 32) ? red[lane] : 0.f;
        for (int off = 2; off > 0; off >>= 1)
            local += __shfl_down_sync(0xFFFFFFFFu, local, off);
        if (lane == 0)
            atomicAdd(out, local * (1.f / (float)(N_PTS * 3)));
    }
}

// ---------------------------------------------------------------------------
extern "C" void kernel_launch(void* const* d_in, const int* in_sizes, int n_in,
                              void* d_out, int out_size) {
    const float* pallet = (const float*)d_in[0];
    const float* comp   = (const float*)d_in[1];
    float* out = (float*)d_out;

    cudaMemsetAsync(out, 0, sizeof(float));
    sort_prep_kernel<<<P_DIM, S_DIM>>>(pallet);
    prep_b_kernel<<<(N_PTS + 255) / 256, 256>>>(comp);
    softmin_kernel<<<dim3(N_PTS / (BLK * Q_PER_THREAD), NCH), BLK>>>();
    reduce_kernel<<<N_PTS / BLK, BLK>>>(out);
}

// round 2
// speedup vs baseline: 1.4703x; 1.4703x over previous
#include <cuda_runtime.h>
#include <cstdint>

// Problem sizes (fixed by reference)
#define S_DIM  1024
#define P_DIM  8
#define N_PTS  8192            // S*P flattened colors
#define L2E    1.4426950408889634f

#define Q_PER_THREAD 8
#define BLK          128
#define NCH          128       // key-axis chunks -> grid 8 x 128 = 1024 blocks (~7/SM)
#define MC           (N_PTS / NCH)   // 64

// Static device scratch (no allocations allowed)
__device__ float4 g_aq[N_PTS];                 // {Ax, Ay, Az, |A|^2}  (A = log2e * sorted clipped palette)
__device__ float4 g_bq[N_PTS];                 // {|B|^2, -2Bx, -2By, -2Bz}  (B = log2e * comp)
__device__ float4 g_scratch[NCH * N_PTS];      // per-chunk partials {sum_w, accx, accy, accz}

// ---------------------------------------------------------------------------
// Phase 1 (fused): blocks [0,64) = palette sort+prep, blocks [64,128) = comp prep.
// Sort: grid (p, sgroup) over 8 columns x 8 groups of 128 rows. Each block
// computes all 1024 luma keys cooperatively, then ranks its own 128 rows.
// ---------------------------------------------------------------------------
__global__ void __launch_bounds__(BLK) prep_kernel(const float* __restrict__ pallet,
                                                   const float* __restrict__ comp) {
    const int bid = blockIdx.x;
    const int t = threadIdx.x;

    if (bid < 64) {
        __shared__ float keys[S_DIM];
        const int p = bid & 7;
        const int sgrp = bid >> 3;

        // Cooperative key computation for the whole column
        for (int s = t; s < S_DIM; s += BLK) {
            const float* src = pallet + (s * P_DIM + p) * 3;
            float x = fminf(fmaxf(src[0] * 0.5f, 0.f), 1.f);
            float y = fminf(fmaxf(src[1] * 0.5f, 0.f), 1.f);
            float z = fminf(fmaxf(src[2] * 0.5f, 0.f), 1.f);
            keys[s] = x * x * 0.299f + y * y * 0.587f + z * z * 0.114f;
        }
        __syncthreads();

        const int s = sgrp * BLK + t;
        const float key = keys[s];

        // Stable rank: #(smaller) + #(equal with lower index). Matches jnp.argsort.
        int rank = 0;
#pragma unroll 8
        for (int j = 0; j < S_DIM; j++) {
            float kj = keys[j];
            rank += (kj < key) || (kj == key && j < s);
        }

        const float* src = pallet + (s * P_DIM + p) * 3;
        float x = fminf(fmaxf(src[0] * 0.5f, 0.f), 1.f);
        float y = fminf(fmaxf(src[1] * 0.5f, 0.f), 1.f);
        float z = fminf(fmaxf(src[2] * 0.5f, 0.f), 1.f);
        const float Ax = x * L2E, Ay = y * L2E, Az = z * L2E;
        g_aq[rank * P_DIM + p] = make_float4(Ax, Ay, Az, Ax * Ax + Ay * Ay + Az * Az);
    } else {
        const int i = (bid - 64) * BLK + t;   // 64 blocks x 128 = 8192
        const float* b = comp + 3 * i;
        float Bx = b[0] * L2E, By = b[1] * L2E, Bz = b[2] * L2E;
        float B2 = Bx * Bx + By * By + Bz * Bz;
        g_bq[i] = make_float4(B2, -2.f * Bx, -2.f * By, -2.f * Bz);
    }
}

// ---------------------------------------------------------------------------
// Phase 2: the 8192x8192 softmin sweep.
// grid (8, NCH). Each thread owns 8 queries, loops over this block's 64-key chunk.
// Per pair: FADD + 3 FMA (sq), FMNMX, MUFU.SQRT, MUFU.EX2(-d), 4 acc FMA/FADD.
// ---------------------------------------------------------------------------
__global__ void __launch_bounds__(BLK) softmin_kernel() {
    __shared__ float4 sb[MC];

    const int m0 = blockIdx.y * MC;
    if (threadIdx.x < MC) sb[threadIdx.x] = g_bq[m0 + threadIdx.x];
    __syncthreads();

    const int q0 = blockIdx.x * (BLK * Q_PER_THREAD) + threadIdx.x * Q_PER_THREAD;

    float Ax[Q_PER_THREAD], Ay[Q_PER_THREAD], Az[Q_PER_THREAD], A2[Q_PER_THREAD];
    float sw[Q_PER_THREAD], cx[Q_PER_THREAD], cy[Q_PER_THREAD], cz[Q_PER_THREAD];
#pragma unroll
    for (int q = 0; q < Q_PER_THREAD; q++) {
        float4 a = g_aq[q0 + q];
        Ax[q] = a.x; Ay[q] = a.y; Az[q] = a.z; A2[q] = a.w;
        sw[q] = 0.f; cx[q] = 0.f; cy[q] = 0.f; cz[q] = 0.f;
    }

#pragma unroll 4
    for (int i = 0; i < MC; i++) {
        const float4 b = sb[i];
#pragma unroll
        for (int q = 0; q < Q_PER_THREAD; q++) {
            // sq' = |A|^2 + |B|^2 - 2 A.B  (= log2e^2 * |a-b|^2)
            float s = fmaf(b.y, Ax[q], fmaf(b.z, Ay[q], fmaf(b.w, Az[q], b.x + A2[q])));
            s = fmaxf(s, 0.f);
            float d;
            asm("sqrt.approx.f32 %0, %1;" : "=f"(d) : "f"(s));    // d = log2e * dist
            float w;
            asm("ex2.approx.f32 %0, %1;" : "=f"(w) : "f"(-d));    // w = exp(-dist)
            sw[q] += w;
            cx[q] = fmaf(w, b.y, cx[q]);   // accumulates w * (-2*log2e*bx) etc.
            cy[q] = fmaf(w, b.z, cy[q]);
            cz[q] = fmaf(w, b.w, cz[q]);
        }
    }

    float4* dst = g_scratch + blockIdx.y * N_PTS + q0;
#pragma unroll
    for (int q = 0; q < Q_PER_THREAD; q++)
        dst[q] = make_float4(sw[q], cx[q], cy[q], cz[q]);
}

// ---------------------------------------------------------------------------
// Phase 3: combine chunk partials (coalesced, warp-cooperative), MSE reduce.
// 256 blocks x 256 threads. Block handles 32 queries; lanes = consecutive q
// (coalesced 512B lines), warps stride over the 128 chunks.
// ---------------------------------------------------------------------------
#define RBLK 256
__global__ void __launch_bounds__(RBLK) reduce_kernel(float* __restrict__ out) {
    const int lane = threadIdx.x & 31;
    const int wid  = threadIdx.x >> 5;            // 0..7
    const int q    = blockIdx.x * 32 + lane;

    float sw = 0.f, cx = 0.f, cy = 0.f, cz = 0.f;
#pragma unroll
    for (int ch = wid; ch < NCH; ch += 8) {
        float4 v = g_scratch[ch * N_PTS + q];
        sw += v.x; cx += v.y; cy += v.z; cz += v.w;
    }

    __shared__ float4 part[8][32];
    part[wid][lane] = make_float4(sw, cx, cy, cz);
    __syncthreads();

    if (wid == 0) {
#pragma unroll
        for (int w = 1; w < 8; w++) {
            float4 v = part[w][lane];
            sw += v.x; cx += v.y; cy += v.z; cz += v.w;
        }
        // closest_c = acc_c / (-2 * log2e * sum_w)
        const float inv = -1.f / (2.f * L2E * sw);
        float clx = cx * inv, cly = cy * inv, clz = cz * inv;

        float4 a = g_aq[q];
        const float invL = 1.f / L2E;
        float ex = a.x * invL - clx;
        float ey = a.y * invL - cly;
        float ez = a.z * invL - clz;
        float local = ex * ex + ey * ey + ez * ez;

        for (int off = 16; off > 0; off >>= 1)
            local += __shfl_down_sync(0xFFFFFFFFu, local, off);
        if (lane == 0)
            atomicAdd(out, local * (1.f / (float)(N_PTS * 3)));
    }
}

// ---------------------------------------------------------------------------
extern "C" void kernel_launch(void* const* d_in, const int* in_sizes, int n_in,
                              void* d_out, int out_size) {
    const float* pallet = (const float*)d_in[0];
    const float* comp   = (const float*)d_in[1];
    float* out = (float*)d_out;

    cudaMemsetAsync(out, 0, sizeof(float));
    prep_kernel<<<128, BLK>>>(pallet, comp);
    softmin_kernel<<<dim3(N_PTS / (BLK * Q_PER_THREAD), NCH), BLK>>>();
    reduce_kernel<<<N_PTS / 32, RBLK>>>(out);
}

// round 3
// speedup vs baseline: 1.6615x; 1.1301x over previous
#include <cuda_runtime.h>
#include <cstdint>

// Problem sizes (fixed by reference)
#define S_DIM  1024
#define P_DIM  8
#define N_PTS  8192            // S*P flattened colors

#define Q_PER_THREAD 8         // 4 packed pairs
#define QP           (Q_PER_THREAD/2)
#define BLK          128
#define NCH          74        // key chunks -> grid 8 x 74 = 592 = 4 blocks/SM exactly
#define MC           111       // ceil(8192/74); last chunk = 81

// degree-5 Chebyshev minimax of exp(-d), d in [0, sqrt(3)], via t = d/0.8660254 - 1
#define TSC  1.1547005f
#define PK0  0.4206284f
#define PK1 -0.3643174f
#define PK2  0.1575913f
#define PK3 -0.0455043f
#define PK4  0.0102308f
#define PK5 -0.0017610f

// Static device scratch (no allocations allowed)
__device__ float4 g_aq[N_PTS];               // sorted: {ax, ay, az, |a|^2}
__device__ float4 g_aqu[N_PTS];              // unsorted (s,p) order
__device__ float4 g_bq[N_PTS];               // {|b|^2, -2bx, -2by, -2bz}
__device__ float  g_keyT[P_DIM * S_DIM];     // keys transposed [p][s]
__device__ float4 g_scratch[NCH * N_PTS];    // per-chunk partials {sum_w, accx, accy, accz}

// ---- packed f32x2 helpers -------------------------------------------------
union f2u { float2 f; unsigned long long u; };
__device__ __forceinline__ float2 ffma2(float2 a, float2 b, float2 c) {
    f2u A, B, C, D; A.f = a; B.f = b; C.f = c;
    asm("fma.rn.f32x2 %0, %1, %2, %3;" : "=l"(D.u) : "l"(A.u), "l"(B.u), "l"(C.u));
    return D.f;
}
__device__ __forceinline__ float2 fadd2(float2 a, float2 b) {
    f2u A, B, D; A.f = a; B.f = b;
    asm("add.rn.f32x2 %0, %1, %2;" : "=l"(D.u) : "l"(A.u), "l"(B.u));
    return D.f;
}
__device__ __forceinline__ float sqrt_ap(float x) {
    float r; asm("sqrt.approx.f32 %0, %1;" : "=f"(r) : "f"(x)); return r;
}

// ---------------------------------------------------------------------------
// Phase 1a: flat prep. 8192 threads: comp quads + palette keys/values.
// ---------------------------------------------------------------------------
__global__ void __launch_bounds__(BLK) prep_all(const float* __restrict__ pallet,
                                                const float* __restrict__ comp) {
    const int i = blockIdx.x * BLK + threadIdx.x;

    // comp -> key/value quad
    float bx = comp[3 * i], by = comp[3 * i + 1], bz = comp[3 * i + 2];
    g_bq[i] = make_float4(bx * bx + by * by + bz * bz, -2.f * bx, -2.f * by, -2.f * bz);

    // palette -> clipped value, luma key (transposed store), unsorted quad
    const int s = i >> 3, p = i & 7;
    float x = fminf(fmaxf(pallet[3 * i] * 0.5f, 0.f), 1.f);
    float y = fminf(fmaxf(pallet[3 * i + 1] * 0.5f, 0.f), 1.f);
    float z = fminf(fmaxf(pallet[3 * i + 2] * 0.5f, 0.f), 1.f);
    g_keyT[p * S_DIM + s] = x * x * 0.299f + y * y * 0.587f + z * z * 0.114f;
    g_aqu[i] = make_float4(x, y, z, x * x + y * y + z * z);
}

// ---------------------------------------------------------------------------
// Phase 1b: stable rank sort. 128 blocks (8 cols x 16 row-groups) x 256 thr
// (64 rows x 4 j-splits). Matches jnp.argsort stability.
// ---------------------------------------------------------------------------
__global__ void __launch_bounds__(256) sort_kernel() {
    __shared__ float skey[S_DIM];
    __shared__ int   part[256];

    const int p = blockIdx.x & 7;
    const int grp = blockIdx.x >> 3;
    const int t = threadIdx.x;
    const int r = t & 63;          // row within group
    const int js = t >> 6;         // j-split 0..3
    const int s = grp * 64 + r;

    for (int j = t; j < S_DIM; j += 256) skey[j] = g_keyT[p * S_DIM + j];
    __syncthreads();

    const float key = skey[s];
    const float4* sk4 = (const float4*)skey;
    int rank = 0;
#pragma unroll 8
    for (int c = 0; c < 64; c++) {
        const int j = js * 256 + c * 4;
        float4 k4 = sk4[js * 64 + c];
        rank += (k4.x < key) || (k4.x == key && (j    ) < s);
        rank += (k4.y < key) || (k4.y == key && (j + 1) < s);
        rank += (k4.z < key) || (k4.z == key && (j + 2) < s);
        rank += (k4.w < key) || (k4.w == key && (j + 3) < s);
    }
    part[t] = rank;
    __syncthreads();

    if (js == 0) {
        rank = part[r] + part[64 + r] + part[128 + r] + part[192 + r];
        g_aq[rank * P_DIM + p] = g_aqu[s * P_DIM + p];
    }
}

// ---------------------------------------------------------------------------
// Phase 2: 8192x8192 softmin sweep, f32x2-packed, 1 MUFU (sqrt) per pair,
// exp(-d) via degree-5 polynomial.
// ---------------------------------------------------------------------------
__global__ void __launch_bounds__(BLK, 4) softmin_kernel() {
    // shared: lane-duplicated key quads: per i, {B2,B2,nx,nx} {ny,ny,nz,nz}
    __shared__ float4 sb[MC * 2];

    const int m0 = blockIdx.y * MC;
    const int mc = min(MC, N_PTS - m0);
    if (threadIdx.x < mc) {
        float4 v = g_bq[m0 + threadIdx.x];
        sb[2 * threadIdx.x]     = make_float4(v.x, v.x, v.y, v.y);
        sb[2 * threadIdx.x + 1] = make_float4(v.z, v.z, v.w, v.w);
    }
    __syncthreads();

    const int q0 = blockIdx.x * (BLK * Q_PER_THREAD) + threadIdx.x * Q_PER_THREAD;

    float2 Ax[QP], Ay[QP], Az[QP], A2[QP];
    float2 sw[QP], cx[QP], cy[QP], cz[QP];
#pragma unroll
    for (int q = 0; q < QP; q++) {
        float4 a0 = g_aq[q0 + 2 * q], a1 = g_aq[q0 + 2 * q + 1];
        Ax[q] = make_float2(a0.x, a1.x);
        Ay[q] = make_float2(a0.y, a1.y);
        Az[q] = make_float2(a0.z, a1.z);
        A2[q] = make_float2(a0.w, a1.w);
        sw[q] = make_float2(0.f, 0.f); cx[q] = sw[q]; cy[q] = sw[q]; cz[q] = sw[q];
    }

    const float2 k0 = make_float2(PK0, PK0), k1 = make_float2(PK1, PK1),
                 k2 = make_float2(PK2, PK2), k3 = make_float2(PK3, PK3),
                 k4 = make_float2(PK4, PK4), k5 = make_float2(PK5, PK5),
                 tsc = make_float2(TSC, TSC), m1 = make_float2(-1.f, -1.f);

#pragma unroll 2
    for (int i = 0; i < mc; i++) {
        float4 u = sb[2 * i], v = sb[2 * i + 1];
        const float2 B2 = make_float2(u.x, u.y);
        const float2 nx = make_float2(u.z, u.w);
        const float2 ny = make_float2(v.x, v.y);
        const float2 nz = make_float2(v.z, v.w);
#pragma unroll
        for (int q = 0; q < QP; q++) {
            float2 sv = ffma2(nx, Ax[q], ffma2(ny, Ay[q], ffma2(nz, Az[q], fadd2(B2, A2[q]))));
            sv.x = fmaxf(sv.x, 0.f);
            sv.y = fmaxf(sv.y, 0.f);
            float2 d = make_float2(sqrt_ap(sv.x), sqrt_ap(sv.y));
            float2 t = ffma2(d, tsc, m1);                        // t = d/0.866 - 1
            float2 w = ffma2(k5, t, k4);                         // Horner
            w = ffma2(w, t, k3);
            w = ffma2(w, t, k2);
            w = ffma2(w, t, k1);
            w = ffma2(w, t, k0);                                 // w ~= exp(-dist)
            sw[q] = fadd2(sw[q], w);
            cx[q] = ffma2(w, nx, cx[q]);                         // accumulates w*(-2bx) etc.
            cy[q] = ffma2(w, ny, cy[q]);
            cz[q] = ffma2(w, nz, cz[q]);
        }
    }

    float4* dst = g_scratch + blockIdx.y * N_PTS + q0;
#pragma unroll
    for (int q = 0; q < QP; q++) {
        dst[2 * q]     = make_float4(sw[q].x, cx[q].x, cy[q].x, cz[q].x);
        dst[2 * q + 1] = make_float4(sw[q].y, cx[q].y, cy[q].y, cz[q].y);
    }
}

// ---------------------------------------------------------------------------
// Phase 3: combine chunk partials (coalesced), MSE reduce.
// 256 blocks x 256 threads; lanes = consecutive q, warps stride chunks.
// ---------------------------------------------------------------------------
#define RBLK 256
__global__ void __launch_bounds__(RBLK) reduce_kernel(float* __restrict__ out) {
    const int lane = threadIdx.x & 31;
    const int wid  = threadIdx.x >> 5;            // 0..7
    const int q    = blockIdx.x * 32 + lane;

    float sw = 0.f, cx = 0.f, cy = 0.f, cz = 0.f;
    for (int ch = wid; ch < NCH; ch += 8) {
        float4 v = g_scratch[ch * N_PTS + q];
        sw += v.x; cx += v.y; cy += v.z; cz += v.w;
    }

    __shared__ float4 part[8][32];
    part[wid][lane] = make_float4(sw, cx, cy, cz);
    __syncthreads();

    if (wid == 0) {
#pragma unroll
        for (int w = 1; w < 8; w++) {
            float4 v = part[w][lane];
            sw += v.x; cx += v.y; cy += v.z; cz += v.w;
        }
        // closest_c = acc_c / (-2 * sum_w)
        const float inv = -0.5f / sw;
        float clx = cx * inv, cly = cy * inv, clz = cz * inv;

        float4 a = g_aq[q];
        float ex = a.x - clx, ey = a.y - cly, ez = a.z - clz;
        float local = ex * ex + ey * ey + ez * ez;

        for (int off = 16; off > 0; off >>= 1)
            local += __shfl_down_sync(0xFFFFFFFFu, local, off);
        if (lane == 0)
            atomicAdd(out, local * (1.f / (float)(N_PTS * 3)));
    }
}

// ---------------------------------------------------------------------------
extern "C" void kernel_launch(void* const* d_in, const int* in_sizes, int n_in,
                              void* d_out, int out_size) {
    const float* pallet = (const float*)d_in[0];
    const float* comp   = (const float*)d_in[1];
    float* out = (float*)d_out;

    cudaMemsetAsync(out, 0, sizeof(float));
    prep_all<<<N_PTS / BLK, BLK>>>(pallet, comp);
    sort_kernel<<<128, 256>>>();
    softmin_kernel<<<dim3(N_PTS / (BLK * Q_PER_THREAD), NCH), BLK>>>();
    reduce_kernel<<<N_PTS / 32, RBLK>>>(out);
}

// round 5
// speedup vs baseline: 1.7842x; 1.0738x over previous
#include <cuda_runtime.h>
#include <cstdint>

// Problem sizes (fixed by reference)
#define S_DIM  1024
#define P_DIM  8
#define N_PTS  8192            // S*P flattened colors

#define Q_PER_THREAD 8         // 4 packed pairs
#define QP           (Q_PER_THREAD/2)
#define BLK          128
#define NCH          74        // key chunks -> grid 8 x 74 = 592 = 4 blocks/SM exactly
#define MC           111       // ceil(8192/74); last chunk = 81

// Coordinates are pre-scaled by TSC = 2/sqrt(3), so u = sqrt(s') = dist*TSC in [0,2].
// exp(-dist) ~= q(u), degree-5 minimax in monomial basis (Horner: 5 ffma2, no shift op).
#define TSC   1.1547005f
#define ITSC  0.8660254f
#define Q0    1.0000332f
#define Q1   -0.8657411f
#define Q2    0.3730990f
#define Q3   -0.1040375f
#define Q4    0.0190358f
#define Q5   -0.0017610f
// MUFU path: exp(-dist) = ex2(-log2(e)/TSC * u)
#define CEX  -1.2494113f

// Static device scratch (no allocations allowed)
__device__ float4 g_aq[N_PTS];               // sorted: {Ax, Ay, Az, |A|^2},  A = TSC*a
__device__ float4 g_aqu[N_PTS];              // unsorted (s,p) order
__device__ float4 g_bq[N_PTS];               // {|B|^2, -2Bx, -2By, -2Bz},   B = TSC*b
__device__ float  g_keyT[P_DIM * S_DIM];     // keys transposed [p][s]
__device__ float4 g_scratch[NCH * N_PTS];    // per-chunk partials {sum_w, accx, accy, accz}

// ---- packed f32x2 helpers -------------------------------------------------
union f2u { float2 f; unsigned long long u; };
__device__ __forceinline__ float2 ffma2(float2 a, float2 b, float2 c) {
    f2u A, B, C, D; A.f = a; B.f = b; C.f = c;
    asm("fma.rn.f32x2 %0, %1, %2, %3;" : "=l"(D.u) : "l"(A.u), "l"(B.u), "l"(C.u));
    return D.f;
}
__device__ __forceinline__ float2 fadd2(float2 a, float2 b) {
    f2u A, B, D; A.f = a; B.f = b;
    asm("add.rn.f32x2 %0, %1, %2;" : "=l"(D.u) : "l"(A.u), "l"(B.u));
    return D.f;
}
__device__ __forceinline__ float2 fmul2(float2 a, float2 b) {
    f2u A, B, D; A.f = a; B.f = b;
    asm("mul.rn.f32x2 %0, %1, %2;" : "=l"(D.u) : "l"(A.u), "l"(B.u));
    return D.f;
}
__device__ __forceinline__ float sqrt_ap(float x) {
    float r; asm("sqrt.approx.f32 %0, %1;" : "=f"(r) : "f"(x)); return r;
}
__device__ __forceinline__ float ex2_ap(float x) {
    float r; asm("ex2.approx.f32 %0, %1;" : "=f"(r) : "f"(x)); return r;
}

// ---------------------------------------------------------------------------
// Phase 1a: flat prep. 8192 threads: comp quads + palette keys/values.
// Thread 0 also zero-inits the output accumulator (replaces a memset node).
// ---------------------------------------------------------------------------
__global__ void __launch_bounds__(BLK) prep_all(const float* __restrict__ pallet,
                                                const float* __restrict__ comp,
                                                float* __restrict__ out) {
    const int i = blockIdx.x * BLK + threadIdx.x;
    if (i == 0) out[0] = 0.f;

    // comp -> key/value quad (TSC-scaled)
    float bx = comp[3 * i] * TSC, by = comp[3 * i + 1] * TSC, bz = comp[3 * i + 2] * TSC;
    g_bq[i] = make_float4(bx * bx + by * by + bz * bz, -2.f * bx, -2.f * by, -2.f * bz);

    // palette -> clipped value, luma key (transposed store), unsorted scaled quad
    const int s = i >> 3, p = i & 7;
    float x = fminf(fmaxf(pallet[3 * i] * 0.5f, 0.f), 1.f);
    float y = fminf(fmaxf(pallet[3 * i + 1] * 0.5f, 0.f), 1.f);
    float z = fminf(fmaxf(pallet[3 * i + 2] * 0.5f, 0.f), 1.f);
    g_keyT[p * S_DIM + s] = x * x * 0.299f + y * y * 0.587f + z * z * 0.114f;
    float ax = x * TSC, ay = y * TSC, az = z * TSC;
    g_aqu[i] = make_float4(ax, ay, az, ax * ax + ay * ay + az * az);
}

// ---------------------------------------------------------------------------
// Phase 1b: stable rank sort. 128 blocks (8 cols x 16 row-groups) x 256 thr
// (64 rows x 4 j-splits). Matches jnp.argsort stability.
// ---------------------------------------------------------------------------
__global__ void __launch_bounds__(256) sort_kernel() {
    __shared__ float skey[S_DIM];
    __shared__ int   part[256];

    const int p = blockIdx.x & 7;
    const int grp = blockIdx.x >> 3;
    const int t = threadIdx.x;
    const int r = t & 63;          // row within group
    const int js = t >> 6;         // j-split 0..3
    const int s = grp * 64 + r;

    for (int j = t; j < S_DIM; j += 256) skey[j] = g_keyT[p * S_DIM + j];
    __syncthreads();

    const float key = skey[s];
    const float4* sk4 = (const float4*)skey;
    int rank = 0;
#pragma unroll 8
    for (int c = 0; c < 64; c++) {
        const int j = js * 256 + c * 4;
        float4 k4 = sk4[js * 64 + c];
        rank += (k4.x < key) || (k4.x == key && (j    ) < s);
        rank += (k4.y < key) || (k4.y == key && (j + 1) < s);
        rank += (k4.z < key) || (k4.z == key && (j + 2) < s);
        rank += (k4.w < key) || (k4.w == key && (j + 3) < s);
    }
    part[t] = rank;
    __syncthreads();

    if (js == 0) {
        rank = part[r] + part[64 + r] + part[128 + r] + part[192 + r];
        g_aq[rank * P_DIM + p] = g_aqu[s * P_DIM + p];
    }
}

// ---------------------------------------------------------------------------
// Phase 2: 8192x8192 softmin sweep, f32x2-packed.
// Keys alternate between the poly path (FMA-heavy) and the MUFU ex2 path
// (MUFU-heavy) to balance the fma and xu pipes.
// ---------------------------------------------------------------------------
struct SoftState {
    float2 Ax[QP], Ay[QP], Az[QP], A2[QP];
    float2 sw[QP], cx[QP], cy[QP], cz[QP];
};

template<bool MUFU_PATH>
__device__ __forceinline__ void soft_body(const float4* __restrict__ sb, int i, SoftState& st) {
    const float4 u4 = sb[2 * i], v4 = sb[2 * i + 1];
    const float2 B2 = make_float2(u4.x, u4.y);
    const float2 nx = make_float2(u4.z, u4.w);
    const float2 ny = make_float2(v4.x, v4.y);
    const float2 nz = make_float2(v4.z, v4.w);
#pragma unroll
    for (int q = 0; q < QP; q++) {
        // s' = |A|^2 + |B|^2 - 2 A.B  (= TSC^2 * |a-b|^2); fabs folds into MUFU
        float2 sv = ffma2(nx, st.Ax[q], ffma2(ny, st.Ay[q], ffma2(nz, st.Az[q], fadd2(B2, st.A2[q]))));
        float2 u = make_float2(sqrt_ap(fabsf(sv.x)), sqrt_ap(fabsf(sv.y)));  // u = TSC*dist
        float2 w;
        if (MUFU_PATH) {
            float2 e = fmul2(u, make_float2(CEX, CEX));
            w = make_float2(ex2_ap(e.x), ex2_ap(e.y));                        // exp(-dist)
        } else {
            w = ffma2(make_float2(Q5, Q5), u, make_float2(Q4, Q4));           // Horner in u
            w = ffma2(w, u, make_float2(Q3, Q3));
            w = ffma2(w, u, make_float2(Q2, Q2));
            w = ffma2(w, u, make_float2(Q1, Q1));
            w = ffma2(w, u, make_float2(Q0, Q0));                             // ~= exp(-dist)
        }
        st.sw[q] = fadd2(st.sw[q], w);
        st.cx[q] = ffma2(w, nx, st.cx[q]);   // accumulates w*(-2*TSC*bx) etc.
        st.cy[q] = ffma2(w, ny, st.cy[q]);
        st.cz[q] = ffma2(w, nz, st.cz[q]);
    }
}

__global__ void __launch_bounds__(BLK, 4) softmin_kernel() {
    // shared: lane-duplicated key quads: per i, {B2,B2,nx,nx} {ny,ny,nz,nz}
    __shared__ float4 sb[MC * 2];

    const int m0 = blockIdx.y * MC;
    const int mc = min(MC, N_PTS - m0);
    if (threadIdx.x < mc) {
        float4 v = g_bq[m0 + threadIdx.x];
        sb[2 * threadIdx.x]     = make_float4(v.x, v.x, v.y, v.y);
        sb[2 * threadIdx.x + 1] = make_float4(v.z, v.z, v.w, v.w);
    }
    __syncthreads();

    const int q0 = blockIdx.x * (BLK * Q_PER_THREAD) + threadIdx.x * Q_PER_THREAD;

    SoftState st;
#pragma unroll
    for (int q = 0; q < QP; q++) {
        float4 a0 = g_aq[q0 + 2 * q], a1 = g_aq[q0 + 2 * q + 1];
        st.Ax[q] = make_float2(a0.x, a1.x);
        st.Ay[q] = make_float2(a0.y, a1.y);
        st.Az[q] = make_float2(a0.z, a1.z);
        st.A2[q] = make_float2(a0.w, a1.w);
        st.sw[q] = make_float2(0.f, 0.f);
        st.cx[q] = st.sw[q]; st.cy[q] = st.sw[q]; st.cz[q] = st.sw[q];
    }

    int i = 0;
    for (; i + 2 <= mc; i += 2) {
        soft_body<false>(sb, i, st);      // poly path (fma-heavy)
        soft_body<true>(sb, i + 1, st);   // mufu path (xu-heavy)
    }
    if (i < mc) soft_body<false>(sb, i, st);

    float4* dst = g_scratch + blockIdx.y * N_PTS + q0;
#pragma unroll
    for (int q = 0; q < QP; q++) {
        dst[2 * q]     = make_float4(st.sw[q].x, st.cx[q].x, st.cy[q].x, st.cz[q].x);
        dst[2 * q + 1] = make_float4(st.sw[q].y, st.cx[q].y, st.cy[q].y, st.cz[q].y);
    }
}

// ---------------------------------------------------------------------------
// Phase 3: combine chunk partials (coalesced), MSE reduce.
// 256 blocks x 512 threads (16 warps): lanes = consecutive q, warps stride
// the 74 chunks (<=5 serial loads each) for high MLP.
// ---------------------------------------------------------------------------
#define RBLK 512
#define RWARPS (RBLK / 32)
__global__ void __launch_bounds__(RBLK) reduce_kernel(float* __restrict__ out) {
    const int lane = threadIdx.x & 31;
    const int wid  = threadIdx.x >> 5;            // 0..15
    const int q    = blockIdx.x * 32 + lane;

    float sw = 0.f, cx = 0.f, cy = 0.f, cz = 0.f;
#pragma unroll
    for (int ch = wid; ch < NCH; ch += RWARPS) {
        float4 v = g_scratch[ch * N_PTS + q];
        sw += v.x; cx += v.y; cy += v.z; cz += v.w;
    }

    __shared__ float4 part[RWARPS][32];
    part[wid][lane] = make_float4(sw, cx, cy, cz);
    __syncthreads();

    if (wid == 0) {
#pragma unroll
        for (int w = 1; w < RWARPS; w++) {
            float4 v = part[w][lane];
            sw += v.x; cx += v.y; cy += v.z; cz += v.w;
        }
        // closest_c = acc_c / (-2 * TSC * sum_w)   (acc holds w * -2*TSC*b)
        const float inv = -1.f / (2.f * TSC * sw);
        float clx = cx * inv, cly = cy * inv, clz = cz * inv;

        float4 a = g_aq[q];                        // TSC-scaled
        float ex = a.x * ITSC - clx;
        float ey = a.y * ITSC - cly;
        float ez = a.z * ITSC - clz;
        float local = ex * ex + ey * ey + ez * ez;

        for (int off = 16; off > 0; off >>= 1)
            local += __shfl_down_sync(0xFFFFFFFFu, local, off);
        if (lane == 0)
            atomicAdd(out, local * (1.f / (float)(N_PTS * 3)));
    }
}

// ---------------------------------------------------------------------------
extern "C" void kernel_launch(void* const* d_in, const int* in_sizes, int n_in,
                              void* d_out, int out_size) {
    const float* pallet = (const float*)d_in[0];
    const float* comp   = (const float*)d_in[1];
    float* out = (float*)d_out;

    prep_all<<<N_PTS / BLK, BLK>>>(pallet, comp, out);
    sort_kernel<<<128, 256>>>();
    softmin_kernel<<<dim3(N_PTS / (BLK * Q_PER_THREAD), NCH), BLK>>>();
    reduce_kernel<<<N_PTS / 32, RBLK>>>(out);
}

// round 6
// speedup vs baseline: 1.8049x; 1.0116x over previous
#include <cuda_runtime.h>
#include <cstdint>

// Problem sizes (fixed by reference)
#define S_DIM  1024
#define P_DIM  8
#define N_PTS  8192            // S*P flattened colors

#define Q_PER_THREAD 8         // 4 packed pairs
#define QP           (Q_PER_THREAD/2)
#define BLK          128
#define NCH          74        // key chunks -> grid 8 x 74 = 592 = 4 blocks/SM exactly
#define MC           111       // ceil(8192/74); last chunk = 81

// Coordinates pre-scaled by LG2E so u = sqrt(s') = log2(e)*dist and
// exp(-dist) = ex2(-u): zero extra FMA for the exponent argument.
#define LG2E  1.4426950408889634f
#define ILG2E 0.6931471805599453f

// Static device scratch (no allocations allowed)
__device__ float4 g_aq[N_PTS];               // sorted: {Ax, Ay, Az, |A|^2},  A = LG2E*a
__device__ float4 g_aqu[N_PTS];              // unsorted (s,p) order
__device__ float4 g_bq[N_PTS];               // {|B|^2, -2Bx, -2By, -2Bz},   B = LG2E*b
__device__ float  g_keyT[P_DIM * S_DIM];     // keys transposed [p][s]
__device__ float4 g_scratch[NCH * N_PTS];    // per-chunk partials {sum_w, accx, accy, accz}

// ---- packed f32x2 helpers -------------------------------------------------
union f2u { float2 f; unsigned long long u; };
__device__ __forceinline__ float2 ffma2(float2 a, float2 b, float2 c) {
    f2u A, B, C, D; A.f = a; B.f = b; C.f = c;
    asm("fma.rn.f32x2 %0, %1, %2, %3;" : "=l"(D.u) : "l"(A.u), "l"(B.u), "l"(C.u));
    return D.f;
}
__device__ __forceinline__ float2 fadd2(float2 a, float2 b) {
    f2u A, B, D; A.f = a; B.f = b;
    asm("add.rn.f32x2 %0, %1, %2;" : "=l"(D.u) : "l"(A.u), "l"(B.u));
    return D.f;
}
__device__ __forceinline__ float sqrt_ap(float x) {
    float r; asm("sqrt.approx.f32 %0, %1;" : "=f"(r) : "f"(x)); return r;
}
__device__ __forceinline__ float ex2_ap(float x) {
    float r; asm("ex2.approx.f32 %0, %1;" : "=f"(r) : "f"(x)); return r;
}

// ---------------------------------------------------------------------------
// Phase 1a: flat prep. 8192 threads: comp quads + palette keys/values.
// Thread 0 also zero-inits the output accumulator.
// ---------------------------------------------------------------------------
__global__ void __launch_bounds__(BLK) prep_all(const float* __restrict__ pallet,
                                                const float* __restrict__ comp,
                                                float* __restrict__ out) {
    const int i = blockIdx.x * BLK + threadIdx.x;
    if (i == 0) out[0] = 0.f;

    // comp -> key/value quad (LG2E-scaled)
    float bx = comp[3 * i] * LG2E, by = comp[3 * i + 1] * LG2E, bz = comp[3 * i + 2] * LG2E;
    g_bq[i] = make_float4(bx * bx + by * by + bz * bz, -2.f * bx, -2.f * by, -2.f * bz);

    // palette -> clipped value, luma key (transposed store), unsorted scaled quad
    const int s = i >> 3, p = i & 7;
    float x = fminf(fmaxf(pallet[3 * i] * 0.5f, 0.f), 1.f);
    float y = fminf(fmaxf(pallet[3 * i + 1] * 0.5f, 0.f), 1.f);
    float z = fminf(fmaxf(pallet[3 * i + 2] * 0.5f, 0.f), 1.f);
    g_keyT[p * S_DIM + s] = x * x * 0.299f + y * y * 0.587f + z * z * 0.114f;
    float ax = x * LG2E, ay = y * LG2E, az = z * LG2E;
    g_aqu[i] = make_float4(ax, ay, az, ax * ax + ay * ay + az * az);
}

// ---------------------------------------------------------------------------
// Phase 1b: stable rank sort. 128 blocks (8 cols x 16 row-groups) x 256 thr
// (64 rows x 4 j-splits). Matches jnp.argsort stability.
// ---------------------------------------------------------------------------
__global__ void __launch_bounds__(256) sort_kernel() {
    __shared__ float skey[S_DIM];
    __shared__ int   part[256];

    const int p = blockIdx.x & 7;
    const int grp = blockIdx.x >> 3;
    const int t = threadIdx.x;
    const int r = t & 63;          // row within group
    const int js = t >> 6;         // j-split 0..3
    const int s = grp * 64 + r;

    for (int j = t; j < S_DIM; j += 256) skey[j] = g_keyT[p * S_DIM + j];
    __syncthreads();

    const float key = skey[s];
    const float4* sk4 = (const float4*)skey;
    int rank = 0;
#pragma unroll 8
    for (int c = 0; c < 64; c++) {
        const int j = js * 256 + c * 4;
        float4 k4 = sk4[js * 64 + c];
        rank += (k4.x < key) || (k4.x == key && (j    ) < s);
        rank += (k4.y < key) || (k4.y == key && (j + 1) < s);
        rank += (k4.z < key) || (k4.z == key && (j + 2) < s);
        rank += (k4.w < key) || (k4.w == key && (j + 3) < s);
    }
    part[t] = rank;
    __syncthreads();

    if (js == 0) {
        rank = part[r] + part[64 + r] + part[128 + r] + part[192 + r];
        g_aq[rank * P_DIM + p] = g_aqu[s * P_DIM + p];
    }
}

// ---------------------------------------------------------------------------
// Phase 2: 8192x8192 softmin sweep. Pure MUFU path: per pair,
// 4 dot + 4 acc FMA-slots and 2 MUFU (sqrt, ex2-with-neg) -- both pipes
// balanced at 16 cyc/query/warp.
// ---------------------------------------------------------------------------
__global__ void __launch_bounds__(BLK, 4) softmin_kernel() {
    // shared: lane-duplicated key quads: per i, {B2,B2,nx,nx} {ny,ny,nz,nz}
    __shared__ float4 sb[MC * 2];

    const int m0 = blockIdx.y * MC;
    const int mc = min(MC, N_PTS - m0);
    if (threadIdx.x < mc) {
        float4 v = g_bq[m0 + threadIdx.x];
        sb[2 * threadIdx.x]     = make_float4(v.x, v.x, v.y, v.y);
        sb[2 * threadIdx.x + 1] = make_float4(v.z, v.z, v.w, v.w);
    }
    __syncthreads();

    const int q0 = blockIdx.x * (BLK * Q_PER_THREAD) + threadIdx.x * Q_PER_THREAD;

    float2 Ax[QP], Ay[QP], Az[QP], A2[QP];
    float2 sw[QP], cx[QP], cy[QP], cz[QP];
#pragma unroll
    for (int q = 0; q < QP; q++) {
        float4 a0 = g_aq[q0 + 2 * q], a1 = g_aq[q0 + 2 * q + 1];
        Ax[q] = make_float2(a0.x, a1.x);
        Ay[q] = make_float2(a0.y, a1.y);
        Az[q] = make_float2(a0.z, a1.z);
        A2[q] = make_float2(a0.w, a1.w);
        sw[q] = make_float2(0.f, 0.f);
        cx[q] = sw[q]; cy[q] = sw[q]; cz[q] = sw[q];
    }

#pragma unroll 3
    for (int i = 0; i < mc; i++) {
        const float4 u4 = sb[2 * i], v4 = sb[2 * i + 1];
        const float2 B2 = make_float2(u4.x, u4.y);
        const float2 nx = make_float2(u4.z, u4.w);
        const float2 ny = make_float2(v4.x, v4.y);
        const float2 nz = make_float2(v4.z, v4.w);
#pragma unroll
        for (int q = 0; q < QP; q++) {
            // s' = |A|^2 + |B|^2 - 2 A.B  (= log2e^2 * |a-b|^2)
            float2 sv = ffma2(nx, Ax[q], ffma2(ny, Ay[q], ffma2(nz, Az[q], fadd2(B2, A2[q]))));
            // u = log2e * dist; w = 2^(-u) = exp(-dist). |.| and neg fold into MUFU.
            float2 w = make_float2(ex2_ap(-sqrt_ap(fabsf(sv.x))),
                                   ex2_ap(-sqrt_ap(fabsf(sv.y))));
            sw[q] = fadd2(sw[q], w);
            cx[q] = ffma2(w, nx, cx[q]);   // accumulates w*(-2*LG2E*bx) etc.
            cy[q] = ffma2(w, ny, cy[q]);
            cz[q] = ffma2(w, nz, cz[q]);
        }
    }

    float4* dst = g_scratch + blockIdx.y * N_PTS + q0;
#pragma unroll
    for (int q = 0; q < QP; q++) {
        dst[2 * q]     = make_float4(sw[q].x, cx[q].x, cy[q].x, cz[q].x);
        dst[2 * q + 1] = make_float4(sw[q].y, cx[q].y, cy[q].y, cz[q].y);
    }
}

// ---------------------------------------------------------------------------
// Phase 3: combine chunk partials (coalesced), MSE reduce.
// 256 blocks x 512 threads (16 warps): lanes = consecutive q, warps stride
// the 74 chunks (<=5 independent loads each) for high MLP.
// ---------------------------------------------------------------------------
#define RBLK 512
#define RWARPS (RBLK / 32)
__global__ void __launch_bounds__(RBLK) reduce_kernel(float* __restrict__ out) {
    const int lane = threadIdx.x & 31;
    const int wid  = threadIdx.x >> 5;            // 0..15
    const int q    = blockIdx.x * 32 + lane;

    float sw = 0.f, cx = 0.f, cy = 0.f, cz = 0.f;
#pragma unroll
    for (int ch = wid; ch < NCH; ch += RWARPS) {
        float4 v = g_scratch[ch * N_PTS + q];
        sw += v.x; cx += v.y; cy += v.z; cz += v.w;
    }

    __shared__ float4 part[RWARPS][32];
    part[wid][lane] = make_float4(sw, cx, cy, cz);
    __syncthreads();

    if (wid == 0) {
#pragma unroll
        for (int w = 1; w < RWARPS; w++) {
            float4 v = part[w][lane];
            sw += v.x; cx += v.y; cy += v.z; cz += v.w;
        }
        // closest_c = acc_c / (-2 * LG2E * sum_w)   (acc holds w * -2*LG2E*b)
        const float inv = -1.f / (2.f * LG2E * sw);
        float clx = cx * inv, cly = cy * inv, clz = cz * inv;

        float4 a = g_aq[q];                        // LG2E-scaled
        float ex = a.x * ILG2E - clx;
        float ey = a.y * ILG2E - cly;
        float ez = a.z * ILG2E - clz;
        float local = ex * ex + ey * ey + ez * ez;

        for (int off = 16; off > 0; off >>= 1)
            local += __shfl_down_sync(0xFFFFFFFFu, local, off);
        if (lane == 0)
            atomicAdd(out, local * (1.f / (float)(N_PTS * 3)));
    }
}

// ---------------------------------------------------------------------------
extern "C" void kernel_launch(void* const* d_in, const int* in_sizes, int n_in,
                              void* d_out, int out_size) {
    const float* pallet = (const float*)d_in[0];
    const float* comp   = (const float*)d_in[1];
    float* out = (float*)d_out;

    prep_all<<<N_PTS / BLK, BLK>>>(pallet, comp, out);
    sort_kernel<<<128, 256>>>();
    softmin_kernel<<<dim3(N_PTS / (BLK * Q_PER_THREAD), NCH), BLK>>>();
    reduce_kernel<<<N_PTS / 32, RBLK>>>(out);
}

// round 7
// speedup vs baseline: 1.8732x; 1.0379x over previous
#include <cuda_runtime.h>
#include <cstdint>

// Problem sizes (fixed by reference)
#define S_DIM  1024
#define P_DIM  8
#define N_PTS  8192            // S*P flattened colors

#define Q_PER_THREAD 4         // 2 packed pairs per thread
#define QP           (Q_PER_THREAD/2)
#define BLK          256       // 8 warps/block
#define NCH          74        // key chunks -> grid 8 x 74 = 592 = 4 blocks/SM exactly
                               // -> 1024 thr/SM = 32 warps/SM = 8 warps/SMSP
#define MC           111       // ceil(8192/74); last chunk = 81

// Coordinates pre-scaled by LG2E so u = sqrt(s') = log2(e)*dist and
// exp(-dist) = ex2(-u): zero extra FMA for the exponent argument.
#define LG2E  1.4426950408889634f
#define ILG2E 0.6931471805599453f

// Static device scratch (no allocations allowed)
__device__ float4 g_aq[N_PTS];               // sorted: {Ax, Ay, Az, |A|^2},  A = LG2E*a
__device__ float4 g_aqu[N_PTS];              // unsorted (s,p) order
__device__ float4 g_bq[N_PTS];               // {|B|^2, -2Bx, -2By, -2Bz},   B = LG2E*b
__device__ float  g_keyT[P_DIM * S_DIM];     // keys transposed [p][s]
__device__ float4 g_scratch[NCH * N_PTS];    // per-chunk partials {sum_w, accx, accy, accz}

// ---- packed f32x2 helpers -------------------------------------------------
union f2u { float2 f; unsigned long long u; };
__device__ __forceinline__ float2 ffma2(float2 a, float2 b, float2 c) {
    f2u A, B, C, D; A.f = a; B.f = b; C.f = c;
    asm("fma.rn.f32x2 %0, %1, %2, %3;" : "=l"(D.u) : "l"(A.u), "l"(B.u), "l"(C.u));
    return D.f;
}
__device__ __forceinline__ float2 fadd2(float2 a, float2 b) {
    f2u A, B, D; A.f = a; B.f = b;
    asm("add.rn.f32x2 %0, %1, %2;" : "=l"(D.u) : "l"(A.u), "l"(B.u));
    return D.f;
}
__device__ __forceinline__ float sqrt_ap(float x) {
    float r; asm("sqrt.approx.f32 %0, %1;" : "=f"(r) : "f"(x)); return r;
}
__device__ __forceinline__ float ex2_ap(float x) {
    float r; asm("ex2.approx.f32 %0, %1;" : "=f"(r) : "f"(x)); return r;
}

// ---------------------------------------------------------------------------
// Phase 1a: flat prep. 8192 threads: comp quads + palette keys/values.
// Thread 0 also zero-inits the output accumulator.
// ---------------------------------------------------------------------------
__global__ void __launch_bounds__(128) prep_all(const float* __restrict__ pallet,
                                                const float* __restrict__ comp,
                                                float* __restrict__ out) {
    const int i = blockIdx.x * 128 + threadIdx.x;
    if (i == 0) out[0] = 0.f;

    // comp -> key/value quad (LG2E-scaled)
    float bx = comp[3 * i] * LG2E, by = comp[3 * i + 1] * LG2E, bz = comp[3 * i + 2] * LG2E;
    g_bq[i] = make_float4(bx * bx + by * by + bz * bz, -2.f * bx, -2.f * by, -2.f * bz);

    // palette -> clipped value, luma key (transposed store), unsorted scaled quad
    const int s = i >> 3, p = i & 7;
    float x = fminf(fmaxf(pallet[3 * i] * 0.5f, 0.f), 1.f);
    float y = fminf(fmaxf(pallet[3 * i + 1] * 0.5f, 0.f), 1.f);
    float z = fminf(fmaxf(pallet[3 * i + 2] * 0.5f, 0.f), 1.f);
    g_keyT[p * S_DIM + s] = x * x * 0.299f + y * y * 0.587f + z * z * 0.114f;
    float ax = x * LG2E, ay = y * LG2E, az = z * LG2E;
    g_aqu[i] = make_float4(ax, ay, az, ax * ax + ay * ay + az * az);
}

// ---------------------------------------------------------------------------
// Phase 1b: stable rank sort. 128 blocks (8 cols x 16 row-groups) x 256 thr
// (64 rows x 4 j-splits). Matches jnp.argsort stability.
// ---------------------------------------------------------------------------
__global__ void __launch_bounds__(256) sort_kernel() {
    __shared__ float skey[S_DIM];
    __shared__ int   part[256];

    const int p = blockIdx.x & 7;
    const int grp = blockIdx.x >> 3;
    const int t = threadIdx.x;
    const int r = t & 63;          // row within group
    const int js = t >> 6;         // j-split 0..3
    const int s = grp * 64 + r;

    for (int j = t; j < S_DIM; j += 256) skey[j] = g_keyT[p * S_DIM + j];
    __syncthreads();

    const float key = skey[s];
    const float4* sk4 = (const float4*)skey;
    int rank = 0;
#pragma unroll 8
    for (int c = 0; c < 64; c++) {
        const int j = js * 256 + c * 4;
        float4 k4 = sk4[js * 64 + c];
        rank += (k4.x < key) || (k4.x == key && (j    ) < s);
        rank += (k4.y < key) || (k4.y == key && (j + 1) < s);
        rank += (k4.z < key) || (k4.z == key && (j + 2) < s);
        rank += (k4.w < key) || (k4.w == key && (j + 3) < s);
    }
    part[t] = rank;
    __syncthreads();

    if (js == 0) {
        rank = part[r] + part[64 + r] + part[128 + r] + part[192 + r];
        g_aq[rank * P_DIM + p] = g_aqu[s * P_DIM + p];
    }
}

// ---------------------------------------------------------------------------
// Phase 2: 8192x8192 softmin sweep. Same math as round 6 (pure MUFU path),
// but 8 warps/SMSP (was 4) to cover the LDS->dot->sqrt->ex2->acc latency
// chain: BLK=256, Q_PER_THREAD=4, grid 8x74 = 4 blocks/SM = 32 warps/SM.
// ---------------------------------------------------------------------------
__global__ void __launch_bounds__(BLK, 4) softmin_kernel() {
    // shared: lane-duplicated key quads: per i, {B2,B2,nx,nx} {ny,ny,nz,nz}
    __shared__ float4 sb[MC * 2];

    const int m0 = blockIdx.y * MC;
    const int mc = min(MC, N_PTS - m0);
    if (threadIdx.x < mc) {
        float4 v = g_bq[m0 + threadIdx.x];
        sb[2 * threadIdx.x]     = make_float4(v.x, v.x, v.y, v.y);
        sb[2 * threadIdx.x + 1] = make_float4(v.z, v.z, v.w, v.w);
    }
    __syncthreads();

    const int q0 = blockIdx.x * (BLK * Q_PER_THREAD) + threadIdx.x * Q_PER_THREAD;

    float2 Ax[QP], Ay[QP], Az[QP], A2[QP];
    float2 sw[QP], cx[QP], cy[QP], cz[QP];
#pragma unroll
    for (int q = 0; q < QP; q++) {
        float4 a0 = g_aq[q0 + 2 * q], a1 = g_aq[q0 + 2 * q + 1];
        Ax[q] = make_float2(a0.x, a1.x);
        Ay[q] = make_float2(a0.y, a1.y);
        Az[q] = make_float2(a0.z, a1.z);
        A2[q] = make_float2(a0.w, a1.w);
        sw[q] = make_float2(0.f, 0.f);
        cx[q] = sw[q]; cy[q] = sw[q]; cz[q] = sw[q];
    }

#pragma unroll 4
    for (int i = 0; i < mc; i++) {
        const float4 u4 = sb[2 * i], v4 = sb[2 * i + 1];
        const float2 B2 = make_float2(u4.x, u4.y);
        const float2 nx = make_float2(u4.z, u4.w);
        const float2 ny = make_float2(v4.x, v4.y);
        const float2 nz = make_float2(v4.z, v4.w);
#pragma unroll
        for (int q = 0; q < QP; q++) {
            // s' = |A|^2 + |B|^2 - 2 A.B  (= log2e^2 * |a-b|^2)
            float2 sv = ffma2(nx, Ax[q], ffma2(ny, Ay[q], ffma2(nz, Az[q], fadd2(B2, A2[q]))));
            // u = log2e * dist; w = 2^(-u) = exp(-dist). |.| and neg fold into MUFU.
            float2 w = make_float2(ex2_ap(-sqrt_ap(fabsf(sv.x))),
                                   ex2_ap(-sqrt_ap(fabsf(sv.y))));
            sw[q] = fadd2(sw[q], w);
            cx[q] = ffma2(w, nx, cx[q]);   // accumulates w*(-2*LG2E*bx) etc.
            cy[q] = ffma2(w, ny, cy[q]);
            cz[q] = ffma2(w, nz, cz[q]);
        }
    }

    float4* dst = g_scratch + blockIdx.y * N_PTS + q0;
#pragma unroll
    for (int q = 0; q < QP; q++) {
        dst[2 * q]     = make_float4(sw[q].x, cx[q].x, cy[q].x, cz[q].x);
        dst[2 * q + 1] = make_float4(sw[q].y, cx[q].y, cy[q].y, cz[q].y);
    }
}

// ---------------------------------------------------------------------------
// Phase 3: combine chunk partials (coalesced), MSE reduce.
// 256 blocks x 512 threads (16 warps): lanes = consecutive q, warps stride
// the 74 chunks (<=5 independent loads each) for high MLP.
// ---------------------------------------------------------------------------
#define RBLK 512
#define RWARPS (RBLK / 32)
__global__ void __launch_bounds__(RBLK) reduce_kernel(float* __restrict__ out) {
    const int lane = threadIdx.x & 31;
    const int wid  = threadIdx.x >> 5;            // 0..15
    const int q    = blockIdx.x * 32 + lane;

    float sw = 0.f, cx = 0.f, cy = 0.f, cz = 0.f;
#pragma unroll
    for (int ch = wid; ch < NCH; ch += RWARPS) {
        float4 v = g_scratch[ch * N_PTS + q];
        sw += v.x; cx += v.y; cy += v.z; cz += v.w;
    }

    __shared__ float4 part[RWARPS][32];
    part[wid][lane] = make_float4(sw, cx, cy, cz);
    __syncthreads();

    if (wid == 0) {
#pragma unroll
        for (int w = 1; w < RWARPS; w++) {
            float4 v = part[w][lane];
            sw += v.x; cx += v.y; cy += v.z; cz += v.w;
        }
        // closest_c = acc_c / (-2 * LG2E * sum_w)   (acc holds w * -2*LG2E*b)
        const float inv = -1.f / (2.f * LG2E * sw);
        float clx = cx * inv, cly = cy * inv, clz = cz * inv;

        float4 a = g_aq[q];                        // LG2E-scaled
        float ex = a.x * ILG2E - clx;
        float ey = a.y * ILG2E - cly;
        float ez = a.z * ILG2E - clz;
        float local = ex * ex + ey * ey + ez * ez;

        for (int off = 16; off > 0; off >>= 1)
            local += __shfl_down_sync(0xFFFFFFFFu, local, off);
        if (lane == 0)
            atomicAdd(out, local * (1.f / (float)(N_PTS * 3)));
    }
}

// ---------------------------------------------------------------------------
extern "C" void kernel_launch(void* const* d_in, const int* in_sizes, int n_in,
                              void* d_out, int out_size) {
    const float* pallet = (const float*)d_in[0];
    const float* comp   = (const float*)d_in[1];
    float* out = (float*)d_out;

    prep_all<<<N_PTS / 128, 128>>>(pallet, comp, out);
    sort_kernel<<<128, 256>>>();
    softmin_kernel<<<dim3(N_PTS / (BLK * Q_PER_THREAD), NCH), BLK>>>();
    reduce_kernel<<<N_PTS / 32, RBLK>>>(out);
}

// round 8
// speedup vs baseline: 2.0293x; 1.0833x over previous
#include <cuda_runtime.h>
#include <cstdint>

// Problem sizes (fixed by reference)
#define S_DIM  1024
#define P_DIM  8
#define N_PTS  8192            // S*P flattened colors

// NOTE: the reference sorts palette rows per column before the softmin, but
// the final loss is a MEAN over all queries -> permutation-invariant. The
// sort is a no-op on the output scalar and is omitted entirely.

#define Q_PER_THREAD 2         // 1 packed pair per thread
#define BLK          256       // 8 warps/block
#define NCH          37        // key chunks; grid 16 x 37 = 592 = 4 blocks/SM
                               // -> 32 warps/SM = 8 warps/SMSP
#define MC           222       // ceil(8192/37); last chunk = 200

// Coordinates pre-scaled by LG2E so u = sqrt(s') = log2(e)*dist and
// exp(-dist) = ex2(-u): zero extra FMA for the exponent argument.
#define LG2E  1.4426950408889634f
#define ILG2E 0.6931471805599453f

// Static device scratch (no allocations allowed)
__device__ float4 g_aq[N_PTS];               // {Ax, Ay, Az, |A|^2},  A = LG2E*a (unsorted)
__device__ float4 g_bq[N_PTS];               // {|B|^2, -2Bx, -2By, -2Bz},   B = LG2E*b
__device__ float4 g_scratch[NCH * N_PTS];    // per-chunk partials {sum_w, accx, accy, accz}

// ---- packed f32x2 helpers -------------------------------------------------
union f2u { float2 f; unsigned long long u; };
__device__ __forceinline__ float2 ffma2(float2 a, float2 b, float2 c) {
    f2u A, B, C, D; A.f = a; B.f = b; C.f = c;
    asm("fma.rn.f32x2 %0, %1, %2, %3;" : "=l"(D.u) : "l"(A.u), "l"(B.u), "l"(C.u));
    return D.f;
}
__device__ __forceinline__ float2 fadd2(float2 a, float2 b) {
    f2u A, B, D; A.f = a; B.f = b;
    asm("add.rn.f32x2 %0, %1, %2;" : "=l"(D.u) : "l"(A.u), "l"(B.u));
    return D.f;
}
__device__ __forceinline__ float sqrt_ap(float x) {
    float r; asm("sqrt.approx.f32 %0, %1;" : "=f"(r) : "f"(x)); return r;
}
__device__ __forceinline__ float ex2_ap(float x) {
    float r; asm("ex2.approx.f32 %0, %1;" : "=f"(r) : "f"(x)); return r;
}

// ---------------------------------------------------------------------------
// Phase 1: flat prep. 8192 threads: comp quads + palette quads (no sort).
// Thread 0 also zero-inits the output accumulator.
// ---------------------------------------------------------------------------
__global__ void __launch_bounds__(128) prep_all(const float* __restrict__ pallet,
                                                const float* __restrict__ comp,
                                                float* __restrict__ out) {
    const int i = blockIdx.x * 128 + threadIdx.x;
    if (i == 0) out[0] = 0.f;

    // comp -> key/value quad (LG2E-scaled)
    float bx = comp[3 * i] * LG2E, by = comp[3 * i + 1] * LG2E, bz = comp[3 * i + 2] * LG2E;
    g_bq[i] = make_float4(bx * bx + by * by + bz * bz, -2.f * bx, -2.f * by, -2.f * bz);

    // palette -> clipped, scaled quad (order irrelevant to the mean)
    float x = fminf(fmaxf(pallet[3 * i] * 0.5f, 0.f), 1.f);
    float y = fminf(fmaxf(pallet[3 * i + 1] * 0.5f, 0.f), 1.f);
    float z = fminf(fmaxf(pallet[3 * i + 2] * 0.5f, 0.f), 1.f);
    float ax = x * LG2E, ay = y * LG2E, az = z * LG2E;
    g_aq[i] = make_float4(ax, ay, az, ax * ax + ay * ay + az * az);
}

// ---------------------------------------------------------------------------
// Phase 2: 8192x8192 softmin sweep (pure MUFU path; both fma+xu pipes at
// their SIMT floor). grid (16, 37), BLK=256, 2 queries per thread.
// ---------------------------------------------------------------------------
__global__ void __launch_bounds__(BLK, 4) softmin_kernel() {
    // shared: lane-duplicated key quads: per i, {B2,B2,nx,nx} {ny,ny,nz,nz}
    __shared__ float4 sb[MC * 2];

    const int m0 = blockIdx.y * MC;
    const int mc = min(MC, N_PTS - m0);
    if (threadIdx.x < mc) {
        float4 v = g_bq[m0 + threadIdx.x];
        sb[2 * threadIdx.x]     = make_float4(v.x, v.x, v.y, v.y);
        sb[2 * threadIdx.x + 1] = make_float4(v.z, v.z, v.w, v.w);
    }
    __syncthreads();

    const int q0 = blockIdx.x * (BLK * Q_PER_THREAD) + threadIdx.x * Q_PER_THREAD;

    float4 a0 = g_aq[q0], a1 = g_aq[q0 + 1];
    const float2 Ax = make_float2(a0.x, a1.x);
    const float2 Ay = make_float2(a0.y, a1.y);
    const float2 Az = make_float2(a0.z, a1.z);
    const float2 A2 = make_float2(a0.w, a1.w);
    float2 sw = make_float2(0.f, 0.f), cx = sw, cy = sw, cz = sw;

#pragma unroll 4
    for (int i = 0; i < mc; i++) {
        const float4 u4 = sb[2 * i], v4 = sb[2 * i + 1];
        const float2 B2 = make_float2(u4.x, u4.y);
        const float2 nx = make_float2(u4.z, u4.w);
        const float2 ny = make_float2(v4.x, v4.y);
        const float2 nz = make_float2(v4.z, v4.w);
        // s' = |A|^2 + |B|^2 - 2 A.B  (= log2e^2 * |a-b|^2)
        float2 sv = ffma2(nx, Ax, ffma2(ny, Ay, ffma2(nz, Az, fadd2(B2, A2))));
        // u = log2e * dist; w = 2^(-u) = exp(-dist). |.| and neg fold into MUFU.
        float2 w = make_float2(ex2_ap(-sqrt_ap(fabsf(sv.x))),
                               ex2_ap(-sqrt_ap(fabsf(sv.y))));
        sw = fadd2(sw, w);
        cx = ffma2(w, nx, cx);   // accumulates w*(-2*LG2E*bx) etc.
        cy = ffma2(w, ny, cy);
        cz = ffma2(w, nz, cz);
    }

    float4* dst = g_scratch + blockIdx.y * N_PTS + q0;
    dst[0] = make_float4(sw.x, cx.x, cy.x, cz.x);
    dst[1] = make_float4(sw.y, cx.y, cy.y, cz.y);
}

// ---------------------------------------------------------------------------
// Phase 3: combine chunk partials (coalesced), MSE reduce.
// 256 blocks x 512 threads (16 warps): lanes = consecutive q, warps stride
// the 37 chunks (2-3 independent loads each).
// ---------------------------------------------------------------------------
#define RBLK 512
#define RWARPS (RBLK / 32)
__global__ void __launch_bounds__(RBLK) reduce_kernel(float* __restrict__ out) {
    const int lane = threadIdx.x & 31;
    const int wid  = threadIdx.x >> 5;            // 0..15
    const int q    = blockIdx.x * 32 + lane;

    float sw = 0.f, cx = 0.f, cy = 0.f, cz = 0.f;
#pragma unroll
    for (int ch = wid; ch < NCH; ch += RWARPS) {
        float4 v = g_scratch[ch * N_PTS + q];
        sw += v.x; cx += v.y; cy += v.z; cz += v.w;
    }

    __shared__ float4 part[RWARPS][32];
    part[wid][lane] = make_float4(sw, cx, cy, cz);
    __syncthreads();

    if (wid == 0) {
#pragma unroll
        for (int w = 1; w < RWARPS; w++) {
            float4 v = part[w][lane];
            sw += v.x; cx += v.y; cy += v.z; cz += v.w;
        }
        // closest_c = acc_c / (-2 * LG2E * sum_w)   (acc holds w * -2*LG2E*b)
        const float inv = -1.f / (2.f * LG2E * sw);
        float clx = cx * inv, cly = cy * inv, clz = cz * inv;

        float4 a = g_aq[q];                        // LG2E-scaled
        float ex = a.x * ILG2E - clx;
        float ey = a.y * ILG2E - cly;
        float ez = a.z * ILG2E - clz;
        float local = ex * ex + ey * ey + ez * ez;

        for (int off = 16; off > 0; off >>= 1)
            local += __shfl_down_sync(0xFFFFFFFFu, local, off);
        if (lane == 0)
            atomicAdd(out, local * (1.f / (float)(N_PTS * 3)));
    }
}

// ---------------------------------------------------------------------------
extern "C" void kernel_launch(void* const* d_in, const int* in_sizes, int n_in,
                              void* d_out, int out_size) {
    const float* pallet = (const float*)d_in[0];
    const float* comp   = (const float*)d_in[1];
    float* out = (float*)d_out;

    prep_all<<<N_PTS / 128, 128>>>(pallet, comp, out);
    softmin_kernel<<<dim3(N_PTS / (BLK * Q_PER_THREAD), NCH), BLK>>>();
    reduce_kernel<<<N_PTS / 32, RBLK>>>(out);
}

// round 9
// speedup vs baseline: 2.0306x; 1.0007x over previous
#include <cuda_runtime.h>
#include <cstdint>

// Problem sizes (fixed by reference)
#define S_DIM  1024
#define P_DIM  8
#define N_PTS  8192            // S*P flattened colors

// NOTE: the reference sorts palette rows per column before the softmin, but
// the final loss is a MEAN over all queries -> permutation-invariant. The
// sort is a no-op on the output scalar and is omitted entirely.

#define Q_PER_THREAD 2         // 1 packed pair per thread
#define BLK          256       // 8 warps/block
#define NCH          37        // key chunks; grid 16 x 37 = 592 = 4 blocks/SM
                               // -> 32 warps/SM = 8 warps/SMSP
#define MC           222       // ceil(8192/37); last chunk = 200

// Coordinates pre-scaled by LG2E so u = sqrt(s') = log2(e)*dist and
// exp(-dist) = ex2(-u): zero extra FMA for the exponent argument.
#define LG2E  1.4426950408889634f
#define ILG2E 0.6931471805599453f

// Static device scratch (no allocations allowed)
__device__ float4 g_scratch[NCH * N_PTS];    // per-chunk partials {sum_w, accx, accy, accz}

// ---- packed f32x2 helpers -------------------------------------------------
union f2u { float2 f; unsigned long long u; };
__device__ __forceinline__ float2 ffma2(float2 a, float2 b, float2 c) {
    f2u A, B, C, D; A.f = a; B.f = b; C.f = c;
    asm("fma.rn.f32x2 %0, %1, %2, %3;" : "=l"(D.u) : "l"(A.u), "l"(B.u), "l"(C.u));
    return D.f;
}
__device__ __forceinline__ float2 fadd2(float2 a, float2 b) {
    f2u A, B, D; A.f = a; B.f = b;
    asm("add.rn.f32x2 %0, %1, %2;" : "=l"(D.u) : "l"(A.u), "l"(B.u));
    return D.f;
}
__device__ __forceinline__ float sqrt_ap(float x) {
    float r; asm("sqrt.approx.f32 %0, %1;" : "=f"(r) : "f"(x)); return r;
}
__device__ __forceinline__ float ex2_ap(float x) {
    float r; asm("ex2.approx.f32 %0, %1;" : "=f"(r) : "f"(x)); return r;
}

// Clipped, LG2E-scaled palette color for query q.
__device__ __forceinline__ float4 query_quad(const float* __restrict__ pallet, int q) {
    float x = fminf(fmaxf(pallet[3 * q]     * 0.5f, 0.f), 1.f);
    float y = fminf(fmaxf(pallet[3 * q + 1] * 0.5f, 0.f), 1.f);
    float z = fminf(fmaxf(pallet[3 * q + 2] * 0.5f, 0.f), 1.f);
    float ax = x * LG2E, ay = y * LG2E, az = z * LG2E;
    return make_float4(ax, ay, az, ax * ax + ay * ay + az * az);
}

// ---------------------------------------------------------------------------
// Phase 1: 8192x8192 softmin sweep (pure MUFU path; fma+xu pipes co-saturated
// at the SIMT floor). grid (16, 37), BLK=256, 2 queries per thread.
// Each block preps its own key chunk from comp and queries from pallet —
// no separate prep kernel.
// ---------------------------------------------------------------------------
__global__ void __launch_bounds__(BLK, 4) softmin_kernel(const float* __restrict__ pallet,
                                                         const float* __restrict__ comp) {
    // shared: lane-duplicated key quads: per i, {B2,B2,nx,nx} {ny,ny,nz,nz}
    __shared__ float4 sb[MC * 2];

    const int m0 = blockIdx.y * MC;
    const int mc = min(MC, N_PTS - m0);
    if (threadIdx.x < mc) {
        const int m = m0 + threadIdx.x;
        float bx = comp[3 * m] * LG2E, by = comp[3 * m + 1] * LG2E, bz = comp[3 * m + 2] * LG2E;
        float b2 = bx * bx + by * by + bz * bz;
        float nx = -2.f * bx, ny = -2.f * by, nz = -2.f * bz;
        sb[2 * threadIdx.x]     = make_float4(b2, b2, nx, nx);
        sb[2 * threadIdx.x + 1] = make_float4(ny, ny, nz, nz);
    }

    const int q0 = blockIdx.x * (BLK * Q_PER_THREAD) + threadIdx.x * Q_PER_THREAD;
    float4 a0 = query_quad(pallet, q0);
    float4 a1 = query_quad(pallet, q0 + 1);
    const float2 Ax = make_float2(a0.x, a1.x);
    const float2 Ay = make_float2(a0.y, a1.y);
    const float2 Az = make_float2(a0.z, a1.z);
    const float2 A2 = make_float2(a0.w, a1.w);
    float2 sw = make_float2(0.f, 0.f), cx = sw, cy = sw, cz = sw;

    __syncthreads();

#pragma unroll 4
    for (int i = 0; i < mc; i++) {
        const float4 u4 = sb[2 * i], v4 = sb[2 * i + 1];
        const float2 B2 = make_float2(u4.x, u4.y);
        const float2 nx = make_float2(u4.z, u4.w);
        const float2 ny = make_float2(v4.x, v4.y);
        const float2 nz = make_float2(v4.z, v4.w);
        // s' = |A|^2 + |B|^2 - 2 A.B  (= log2e^2 * |a-b|^2)
        float2 sv = ffma2(nx, Ax, ffma2(ny, Ay, ffma2(nz, Az, fadd2(B2, A2))));
        // u = log2e * dist; w = 2^(-u) = exp(-dist). |.| and neg fold into MUFU.
        float2 w = make_float2(ex2_ap(-sqrt_ap(fabsf(sv.x))),
                               ex2_ap(-sqrt_ap(fabsf(sv.y))));
        sw = fadd2(sw, w);
        cx = ffma2(w, nx, cx);   // accumulates w*(-2*LG2E*bx) etc.
        cy = ffma2(w, ny, cy);
        cz = ffma2(w, nz, cz);
    }

    float4* dst = g_scratch + blockIdx.y * N_PTS + q0;
    dst[0] = make_float4(sw.x, cx.x, cy.x, cz.x);
    dst[1] = make_float4(sw.y, cx.y, cy.y, cz.y);
}

// ---------------------------------------------------------------------------
// Phase 2: combine chunk partials (coalesced), MSE reduce.
// 256 blocks x 512 threads (16 warps): lanes = consecutive q, warps stride
// the 37 chunks (2-3 independent loads each). Palette quad recomputed inline.
// ---------------------------------------------------------------------------
#define RBLK 512
#define RWARPS (RBLK / 32)
__global__ void __launch_bounds__(RBLK) reduce_kernel(const float* __restrict__ pallet,
                                                      float* __restrict__ out) {
    const int lane = threadIdx.x & 31;
    const int wid  = threadIdx.x >> 5;            // 0..15
    const int q    = blockIdx.x * 32 + lane;

    float sw = 0.f, cx = 0.f, cy = 0.f, cz = 0.f;
#pragma unroll
    for (int ch = wid; ch < NCH; ch += RWARPS) {
        float4 v = g_scratch[ch * N_PTS + q];
        sw += v.x; cx += v.y; cy += v.z; cz += v.w;
    }

    __shared__ float4 part[RWARPS][32];
    part[wid][lane] = make_float4(sw, cx, cy, cz);
    __syncthreads();

    if (wid == 0) {
#pragma unroll
        for (int w = 1; w < RWARPS; w++) {
            float4 v = part[w][lane];
            sw += v.x; cx += v.y; cy += v.z; cz += v.w;
        }
        // closest_c = acc_c / (-2 * LG2E * sum_w)   (acc holds w * -2*LG2E*b)
        const float inv = -1.f / (2.f * LG2E * sw);
        float clx = cx * inv, cly = cy * inv, clz = cz * inv;

        float4 a = query_quad(pallet, q);          // LG2E-scaled
        float ex = a.x * ILG2E - clx;
        float ey = a.y * ILG2E - cly;
        float ez = a.z * ILG2E - clz;
        float local = ex * ex + ey * ey + ez * ez;

        for (int off = 16; off > 0; off >>= 1)
            local += __shfl_down_sync(0xFFFFFFFFu, local, off);
        if (lane == 0)
            atomicAdd(out, local * (1.f / (float)(N_PTS * 3)));
    }
}

// ---------------------------------------------------------------------------
extern "C" void kernel_launch(void* const* d_in, const int* in_sizes, int n_in,
                              void* d_out, int out_size) {
    const float* pallet = (const float*)d_in[0];
    const float* comp   = (const float*)d_in[1];
    float* out = (float*)d_out;

    cudaMemsetAsync(out, 0, sizeof(float));
    softmin_kernel<<<dim3(N_PTS / (BLK * Q_PER_THREAD), NCH), BLK>>>(pallet, comp);
    reduce_kernel<<<N_PTS / 32, RBLK>>>(pallet, out);
}